// round 8
// baseline (speedup 1.0000x reference)
#include <cuda_runtime.h>
#include <cstdint>
#include <cstddef>
#include <math.h>

#define NMAX 204800
#define GMAX 512

// ---- scratch (no allocations allowed) ----
__device__ __align__(16) float g_xW[(size_t)NMAX * 64]; // per-vertex x @ We1[:128] (raw)
__device__ __align__(16) int   g_mink[(size_t)NMAX * 8];
__device__ __align__(16) int   g_maxk[(size_t)NMAX * 8];
__device__ float g_Sfv[GMAX * 8];
__device__ float g_Smin[GMAX * 8];
__device__ float g_Smax[GMAX * 8];
__device__ float g_h[GMAX * 64];
__device__ float g_bn[128];

__device__ __forceinline__ float sigmoidf_(float x) {
    return 1.0f / (1.0f + __expf(-x));
}

__device__ __forceinline__ unsigned long long pack2(float lo, float hi) {
    unsigned long long r;
    asm("mov.b64 %0, {%1, %2};" : "=l"(r) : "f"(lo), "f"(hi));
    return r;
}
__device__ __forceinline__ void unpack2(unsigned long long v, float& lo, float& hi) {
    asm("mov.b64 {%0, %1}, %2;" : "=f"(lo), "=f"(hi) : "l"(v));
}
__device__ __forceinline__ unsigned long long ffma2(unsigned long long a,
                                                    unsigned long long b,
                                                    unsigned long long c) {
    unsigned long long d;
    asm("fma.rn.f32x2 %0, %1, %2, %3;" : "=l"(d) : "l"(a), "l"(b), "l"(c));
    return d;
}

__device__ __forceinline__ void cp_async16(unsigned dst, const void* src, int nbytes) {
    asm volatile("cp.async.cg.shared.global [%0], [%1], 16, %2;"
                 :: "r"(dst), "l"(src), "r"(nbytes));
}
#define CP_COMMIT() asm volatile("cp.async.commit_group;" ::: "memory")
#define CP_WAIT0()  asm volatile("cp.async.wait_group 0;" ::: "memory")

// init sentinels + Sfv
__global__ void init_kernel(int n8, int g8) {
    int i = blockIdx.x * blockDim.x + threadIdx.x;
    if (i < n8) { g_mink[i] = 0x7f800000; g_maxk[i] = 0; }
    if (i < g8) g_Sfv[i] = 0.0f;
}

// no-op spacers so ncu's fixed capture slot (4th launch) lands on vertex_kernel
__global__ void spacer_kernel() {}
__global__ void spacer2_kernel() {}

// ---------------------------------------------------------------------------
// Persistent vertex kernel (unchanged from R7): FFMA2 GEMM, cp.async
// double-buffered tiles, thread tile 4(M)x8(N).
// ---------------------------------------------------------------------------
#define XS_STRIDE 132
#define XS_FLOATS (128 * XS_STRIDE)      // 16896
#define W_OFF     (2 * XS_FLOATS)        // 33792
#define W2_OFF    (W_OFF + 16384)        // 50176
#define B1_OFF    (W2_OFF + 512)
#define B2_OFF    (B1_OFF + 64)
#define SMV_FLOATS (B2_OFF + 8)          // 50760 floats = 203040 B

__device__ __forceinline__ void prefetch_tile(const float* __restrict__ x,
                                              int v0, int N,
                                              unsigned xs_sm, int tid) {
#pragma unroll
    for (int i = 0; i < 8; ++i) {
        int c = tid + i * 512;           // 0..4095 chunk id
        int row = c >> 5, col4 = c & 31;
        unsigned dst = xs_sm + (unsigned)(row * XS_STRIDE + col4 * 4) * 4u;
        const float* src = x + (size_t)(v0 + row) * 128 + col4 * 4;
        int nb = (v0 + row < N) ? 16 : 0;   // zero-fill OOB rows
        cp_async16(dst, src, nb);
    }
}

__global__ __launch_bounds__(512) void vertex_kernel(
    const float* __restrict__ x, const int* __restrict__ batch,
    const float* __restrict__ W1, const float* __restrict__ b1,
    const float* __restrict__ W2, const float* __restrict__ b2,
    const float* __restrict__ We1, int N, int tiles)
{
    extern __shared__ float sm[];
    float* Wsm = sm + W_OFF;
    float* W2s = sm + W2_OFF;
    float* b1s = sm + B1_OFF;
    float* b2s = sm + B2_OFF;

    const int tid = threadIdx.x;
    const unsigned sm_base = (unsigned)__cvta_generic_to_shared(sm);

    // ---- stage weights once ----
    for (int i = tid; i < 16384; i += 512) {
        int k = i >> 7, n = i & 127;
        Wsm[i] = (n < 64) ? W1[k * 64 + n] : We1[k * 64 + (n - 64)];
    }
    if (tid < 512) W2s[tid] = W2[tid];
    if (tid < 64) b1s[tid] = b1[tid];
    if (tid < 8)  b2s[tid] = b2[tid];

    const int stride = gridDim.x;
    int pp = 0;
    if ((int)blockIdx.x < tiles)
        prefetch_tile(x, blockIdx.x * 128, N, sm_base, tid);
    CP_COMMIT();
    __syncthreads();   // weights + first-tile issue ordering

    const int tx = tid & 15, ty = tid >> 4;   // ty 0..31
    const int m0 = ty * 4, n0 = tx * 8;

    for (int t = blockIdx.x; t < tiles; t += stride) {
        CP_WAIT0();
        __syncthreads();   // xs[pp] ready for everyone; prior epilogue done

        int tn = t + stride;
        if (tn < tiles)
            prefetch_tile(x, tn * 128, N,
                          sm_base + (unsigned)((pp ^ 1) * XS_FLOATS) * 4u, tid);
        CP_COMMIT();

        float* xs   = sm + pp * XS_FLOATS;
        float* hbuf = xs;                   // reused after k-loop
        const int v0 = t * 128;

        unsigned long long acc[4][4];
#pragma unroll
        for (int mi = 0; mi < 4; ++mi)
#pragma unroll
            for (int p = 0; p < 4; ++p) acc[mi][p] = 0ULL;

#pragma unroll 2
        for (int k4 = 0; k4 < 128; k4 += 4) {
            float4 xr[4];
#pragma unroll
            for (int mi = 0; mi < 4; ++mi)
                xr[mi] = *reinterpret_cast<const float4*>(
                    xs + (m0 + mi) * XS_STRIDE + k4);
#pragma unroll
            for (int kk = 0; kk < 4; ++kk) {
                const float* wk = Wsm + ((k4 + kk) << 7) + n0;
                float4 wa = *reinterpret_cast<const float4*>(wk);
                float4 wb = *reinterpret_cast<const float4*>(wk + 4);
                unsigned long long w0  = pack2(wa.x, wa.y);
                unsigned long long w1p = pack2(wa.z, wa.w);
                unsigned long long w2p = pack2(wb.x, wb.y);
                unsigned long long w3p = pack2(wb.z, wb.w);
#pragma unroll
                for (int mi = 0; mi < 4; ++mi) {
                    float xv = (kk == 0) ? xr[mi].x
                             : (kk == 1) ? xr[mi].y
                             : (kk == 2) ? xr[mi].z : xr[mi].w;
                    unsigned long long xx = pack2(xv, xv);
                    acc[mi][0] = ffma2(xx, w0,  acc[mi][0]);
                    acc[mi][1] = ffma2(xx, w1p, acc[mi][1]);
                    acc[mi][2] = ffma2(xx, w2p, acc[mi][2]);
                    acc[mi][3] = ffma2(xx, w3p, acc[mi][3]);
                }
            }
        }
        __syncthreads();   // all reads of xs[pp] done before hbuf overwrite

        if (tx < 8) {
#pragma unroll
            for (int mi = 0; mi < 4; ++mi) {
                float* dst = hbuf + (m0 + mi) * XS_STRIDE + n0;
#pragma unroll
                for (int p = 0; p < 4; ++p) {
                    float lo, hi; unpack2(acc[mi][p], lo, hi);
                    dst[2 * p] = lo; dst[2 * p + 1] = hi;
                }
            }
        } else {
#pragma unroll
            for (int mi = 0; mi < 4; ++mi) {
                int v = v0 + m0 + mi;
                if (v < N) {
                    float* dst = g_xW + (size_t)v * 64 + (n0 - 64);
#pragma unroll
                    for (int p = 0; p < 4; ++p) {
                        float lo, hi; unpack2(acc[mi][p], lo, hi);
                        dst[2 * p] = lo; dst[2 * p + 1] = hi;
                    }
                }
            }
        }
        __syncthreads();

        // fv epilogue: one vertex per thread (tid<128)
        if (tid < 128) {
            int v = v0 + tid;
            bool valid = (v < N);
            float a8[8];
#pragma unroll
            for (int f = 0; f < 8; ++f) a8[f] = b2s[f];
            const float* hr = hbuf + tid * XS_STRIDE;
#pragma unroll 4
            for (int k = 0; k < 64; ++k) {
                float hv = fmaxf(hr[k] + b1s[k], 0.0f);
#pragma unroll
                for (int f = 0; f < 8; ++f) a8[f] = fmaf(hv, W2s[k * 8 + f], a8[f]);
            }
#pragma unroll
            for (int f = 0; f < 8; ++f) a8[f] = valid ? sigmoidf_(a8[f]) : 0.0f;

            const unsigned m = 0xffffffffu;
            int lane = tid & 31;
            int gidx = batch[valid ? v : (N - 1)];
            int gl0  = __shfl_sync(m, gidx, 0);
            bool uni = __all_sync(m, gidx == gl0);
            if (uni) {
#pragma unroll
                for (int f = 0; f < 8; ++f) {
                    float s = a8[f];
                    s += __shfl_xor_sync(m, s, 16);
                    s += __shfl_xor_sync(m, s, 8);
                    s += __shfl_xor_sync(m, s, 4);
                    s += __shfl_xor_sync(m, s, 2);
                    s += __shfl_xor_sync(m, s, 1);
                    if (lane == 0) atomicAdd(&g_Sfv[gl0 * 8 + f], s);
                }
            } else if (valid) {
#pragma unroll
                for (int f = 0; f < 8; ++f) atomicAdd(&g_Sfv[gidx * 8 + f], a8[f]);
            }
        }
        pp ^= 1;
    }
}

// ---------------------------------------------------------------------------
// Edge kernel: 8 lanes cooperate per edge. Restructured to minimize live
// registers (h folded into fe immediately); __launch_bounds__(256,3) for
// 24 warps/SM occupancy.
// ---------------------------------------------------------------------------
__global__ __launch_bounds__(256, 3) void edge_kernel(
    const float* __restrict__ pos, const int* __restrict__ ei,
    const float* __restrict__ We1, const float* __restrict__ be1,
    const float* __restrict__ We2, const float* __restrict__ be2, int E)
{
    __shared__ __align__(16) float w1l[64];
    __shared__ __align__(16) float be1s[64];
    __shared__ float We2s[512];
    __shared__ float be2s[8];

    const int tid = threadIdx.x;
    for (int i = tid; i < 64; i += 256) { w1l[i] = We1[8192 + i]; be1s[i] = be1[i]; }
    for (int i = tid; i < 512; i += 256) We2s[i] = We2[i];
    if (tid < 8) be2s[tid] = be2[tid];
    __syncthreads();

    const int l = tid & 7;
    const int j0 = l * 8;
    const int egrp = (blockIdx.x * 256 + tid) >> 3;
    const int estride = (gridDim.x * 256) >> 3;
    const unsigned fullm = 0xffffffffu;

    for (int e = egrp; e < E; e += estride) {
        int s = ei[e], d = ei[E + e];
        float dx = pos[s * 3 + 0] - pos[d * 3 + 0];
        float dy = pos[s * 3 + 1] - pos[d * 3 + 1];
        float dz = pos[s * 3 + 2] - pos[d * 3 + 2];
        float dist = sqrtf(dx * dx + dy * dy + dz * dz);

        const float4* xs4 = reinterpret_cast<const float4*>(g_xW + (size_t)s * 64 + j0);
        const float4* xd4 = reinterpret_cast<const float4*>(g_xW + (size_t)d * 64 + j0);

        float fe[8];
#pragma unroll
        for (int f = 0; f < 8; ++f) fe[f] = 0.0f;

#pragma unroll
        for (int q = 0; q < 2; ++q) {
            float4 aa = xs4[q], bb = xd4[q];
            float4 wl = *reinterpret_cast<const float4*>(w1l + j0 + 4 * q);
            float4 bv = *reinterpret_cast<const float4*>(be1s + j0 + 4 * q);
            float h0 = fmaxf(fmaf(dist, wl.x, aa.x + bb.x) + bv.x, 0.0f);
            float h1 = fmaxf(fmaf(dist, wl.y, aa.y + bb.y) + bv.y, 0.0f);
            float h2 = fmaxf(fmaf(dist, wl.z, aa.z + bb.z) + bv.z, 0.0f);
            float h3 = fmaxf(fmaf(dist, wl.w, aa.w + bb.w) + bv.w, 0.0f);
            const float* w0r = We2s + (j0 + 4 * q) * 8;
#pragma unroll
            for (int f = 0; f < 8; ++f) {
                float acc = fmaf(h0, w0r[f], fe[f]);
                acc = fmaf(h1, w0r[8 + f], acc);
                acc = fmaf(h2, w0r[16 + f], acc);
                fe[f] = fmaf(h3, w0r[24 + f], acc);
            }
        }
#pragma unroll
        for (int f = 0; f < 8; ++f) {
            float v = fe[f];
            v += __shfl_xor_sync(fullm, v, 4);
            v += __shfl_xor_sync(fullm, v, 2);
            v += __shfl_xor_sync(fullm, v, 1);
            fe[f] = v;
        }
        int key = __float_as_int(sigmoidf_(fe[l] + be2s[l]));
        atomicMin(g_mink + (size_t)s * 8 + l, key);
        atomicMin(g_mink + (size_t)d * 8 + l, key);
        atomicMax(g_maxk + (size_t)s * 8 + l, key);
        atomicMax(g_maxk + (size_t)d * 8 + l, key);
    }
}

// ---------------------------------------------------------------------------
// Per-graph vertex reduce: fixup sentinels -> 1.0, sum dmin/dmax per graph
// ---------------------------------------------------------------------------
__global__ __launch_bounds__(256) void vreduce_kernel(const int* __restrict__ vs)
{
    __shared__ float rn[8], rx[8];
    const int tid = threadIdx.x, g = blockIdx.x;
    const int v0 = vs[g], v1 = vs[g + 1];
    if (tid < 8) { rn[tid] = 0.0f; rx[tid] = 0.0f; }
    __syncthreads();

    float ln[8], lx[8];
#pragma unroll
    for (int f = 0; f < 8; ++f) { ln[f] = 0.0f; lx[f] = 0.0f; }
    for (int v = v0 + tid; v < v1; v += 256) {
        const int4* mn = reinterpret_cast<const int4*>(g_mink + (size_t)v * 8);
        const int4* mx = reinterpret_cast<const int4*>(g_maxk + (size_t)v * 8);
        int4 a = mn[0], b = mn[1], c = mx[0], d = mx[1];
        ln[0] += (a.x == 0x7f800000) ? 1.0f : __int_as_float(a.x);
        ln[1] += (a.y == 0x7f800000) ? 1.0f : __int_as_float(a.y);
        ln[2] += (a.z == 0x7f800000) ? 1.0f : __int_as_float(a.z);
        ln[3] += (a.w == 0x7f800000) ? 1.0f : __int_as_float(a.w);
        ln[4] += (b.x == 0x7f800000) ? 1.0f : __int_as_float(b.x);
        ln[5] += (b.y == 0x7f800000) ? 1.0f : __int_as_float(b.y);
        ln[6] += (b.z == 0x7f800000) ? 1.0f : __int_as_float(b.z);
        ln[7] += (b.w == 0x7f800000) ? 1.0f : __int_as_float(b.w);
        lx[0] += (c.x == 0) ? 1.0f : __int_as_float(c.x);
        lx[1] += (c.y == 0) ? 1.0f : __int_as_float(c.y);
        lx[2] += (c.z == 0) ? 1.0f : __int_as_float(c.z);
        lx[3] += (c.w == 0) ? 1.0f : __int_as_float(c.w);
        lx[4] += (d.x == 0) ? 1.0f : __int_as_float(d.x);
        lx[5] += (d.y == 0) ? 1.0f : __int_as_float(d.y);
        lx[6] += (d.z == 0) ? 1.0f : __int_as_float(d.z);
        lx[7] += (d.w == 0) ? 1.0f : __int_as_float(d.w);
    }
    const unsigned m = 0xffffffffu;
    int lane = tid & 31;
#pragma unroll
    for (int f = 0; f < 8; ++f) {
        float s = ln[f];
        s += __shfl_xor_sync(m, s, 16); s += __shfl_xor_sync(m, s, 8);
        s += __shfl_xor_sync(m, s, 4);  s += __shfl_xor_sync(m, s, 2);
        s += __shfl_xor_sync(m, s, 1);
        if (lane == 0) atomicAdd(&rn[f], s);
        float t = lx[f];
        t += __shfl_xor_sync(m, t, 16); t += __shfl_xor_sync(m, t, 8);
        t += __shfl_xor_sync(m, t, 4);  t += __shfl_xor_sync(m, t, 2);
        t += __shfl_xor_sync(m, t, 1);
        if (lane == 0) atomicAdd(&rx[f], t);
    }
    __syncthreads();
    if (tid < 8) { g_Smin[g * 8 + tid] = rn[tid]; g_Smax[g * 8 + tid] = rx[tid]; }
}

// h = x0 + x1 (pre-BN)
__global__ void f1_kernel(const float* __restrict__ Wd0, const float* __restrict__ bd0,
                          const float* __restrict__ Wd1, const float* __restrict__ bd1,
                          const int* __restrict__ vs, const int* __restrict__ es)
{
    int g = blockIdx.x, o = threadIdx.x;
    float a = 0.0f;
#pragma unroll
    for (int f = 0; f < 8; ++f) {
        float sf = g_Sfv[g * 8 + f];
        float sx = g_Smax[g * 8 + f];
        float sn = g_Smin[g * 8 + f];
        a = fmaf(sf, Wd0[(4 * f + 1) * 64 + o], a);
        a = fmaf(sx, Wd0[(4 * f + 2) * 64 + o], a);
        a = fmaf(sn, Wd0[(4 * f + 3) * 64 + o], a);
    }
    int nv = vs[g + 1] - vs[g];
    int ne = es[g + 1] - es[g];
    float x0 = a / (float)nv + bd0[o];
    float x1 = (ne - (nv - 1) > 0)
                   ? (Wd1[64 + o] + Wd1[128 + o] + Wd1[192 + o] + bd1[o])
                   : 0.0f;
    g_h[g * 64 + o] = x0 + x1;
}

// BatchNorm stats (two-pass)
__global__ void bn_kernel(int G)
{
    __shared__ float ps[512];
    __shared__ float mu_s[64];
    int t = threadIdx.x, o = t & 63, grp = t >> 6;
    float s = 0.0f;
    for (int r = grp; r < G; r += 8) s += g_h[r * 64 + o];
    ps[t] = s;
    __syncthreads();
    if (t < 64) {
        float S = 0.0f;
        for (int k = 0; k < 8; ++k) S += ps[k * 64 + o];
        mu_s[o] = S / (float)G;
    }
    __syncthreads();
    float mu = mu_s[o];
    s = 0.0f;
    for (int r = grp; r < G; r += 8) { float d = g_h[r * 64 + o] - mu; s = fmaf(d, d, s); }
    ps[t] = s;
    __syncthreads();
    if (t < 64) {
        float S = 0.0f;
        for (int k = 0; k < 8; ++k) S += ps[k * 64 + o];
        g_bn[o] = mu_s[o];
        g_bn[64 + o] = rsqrtf(S / (float)G + 1e-5f);
    }
}

// normalize + out MLP
__global__ __launch_bounds__(1024) void out_kernel(
    const float* __restrict__ gamma, const float* __restrict__ beta,
    const float* __restrict__ Wo1, const float* __restrict__ bo1,
    const float* __restrict__ Wo2, const float* __restrict__ bo2,
    float* __restrict__ out, int G)
{
    __shared__ float hn[16][64];
    __shared__ float t1[16][64];
    int t = threadIdx.x, gl = t >> 6, o = t & 63;
    int g = blockIdx.x * 16 + gl;
    float v = 0.0f;
    if (g < G) v = (g_h[g * 64 + o] - g_bn[o]) * g_bn[64 + o] * gamma[o] + beta[o];
    hn[gl][o] = v;
    __syncthreads();
    float a = bo1[o];
#pragma unroll 8
    for (int k = 0; k < 64; ++k) a = fmaf(hn[gl][k], Wo1[k * 64 + o], a);
    t1[gl][o] = fmaxf(a, 0.0f);
    __syncthreads();
    float b = bo2[o];
#pragma unroll 8
    for (int k = 0; k < 64; ++k) b = fmaf(t1[gl][k], Wo2[k * 64 + o], b);
    if (g < G) out[g * 64 + o] = b;
}

extern "C" void kernel_launch(void* const* d_in, const int* in_sizes, int n_in,
                              void* d_out, int out_size)
{
    const float* x     = (const float*)d_in[0];
    const float* pos   = (const float*)d_in[1];
    const int*   ei    = (const int*)d_in[2];
    const int*   vs    = (const int*)d_in[3];
    const int*   es    = (const int*)d_in[4];
    const int*   batch = (const int*)d_in[5];
    const float* W1  = (const float*)d_in[6];
    const float* b1  = (const float*)d_in[7];
    const float* W2  = (const float*)d_in[8];
    const float* b2  = (const float*)d_in[9];
    const float* We1 = (const float*)d_in[10];
    const float* be1 = (const float*)d_in[11];
    const float* We2 = (const float*)d_in[12];
    const float* be2 = (const float*)d_in[13];
    const float* Wd0 = (const float*)d_in[14];
    const float* bd0 = (const float*)d_in[15];
    const float* Wd1 = (const float*)d_in[16];
    const float* bd1 = (const float*)d_in[17];
    const float* gm  = (const float*)d_in[18];
    const float* bt  = (const float*)d_in[19];
    const float* Wo1 = (const float*)d_in[20];
    const float* bo1 = (const float*)d_in[21];
    const float* Wo2 = (const float*)d_in[22];
    const float* bo2 = (const float*)d_in[23];

    int N = in_sizes[0] / 128;
    int E = in_sizes[2] / 2;
    int G = out_size / 64;
    int tiles = (N + 127) / 128;

    init_kernel<<<(N * 8 + 255) / 256, 256>>>(N * 8, G * 8);   // launch 1
    spacer_kernel<<<1, 32>>>();                                 // launch 2
    spacer2_kernel<<<1, 32>>>();                                // launch 3

    size_t smv = (size_t)SMV_FLOATS * sizeof(float);
    cudaFuncSetAttribute(vertex_kernel, cudaFuncAttributeMaxDynamicSharedMemorySize, (int)smv);
    vertex_kernel<<<148, 512, smv>>>(x, batch, W1, b1, W2, b2, We1, N, tiles); // launch 4 (ncu slot)

    edge_kernel<<<1024, 256>>>(pos, ei, We1, be1, We2, be2, E); // launch 5
    vreduce_kernel<<<G, 256>>>(vs);
    f1_kernel<<<G, 64>>>(Wd0, bd0, Wd1, bd1, vs, es);
    bn_kernel<<<1, 512>>>(G);
    out_kernel<<<(G + 15) / 16, 1024>>>(gm, bt, Wo1, bo1, Wo2, bo2, (float*)d_out, G);
}

// round 9
// speedup vs baseline: 1.3035x; 1.3035x over previous
#include <cuda_runtime.h>
#include <cstdint>
#include <cstddef>
#include <math.h>

#define NMAX 204800
#define GMAX 512

// ---- scratch (no allocations allowed) ----
__device__ __align__(16) float g_xW[(size_t)NMAX * 64]; // per-vertex x @ We1[:128] (raw)
__device__ __align__(16) int   g_mink[(size_t)NMAX * 8];
__device__ __align__(16) int   g_maxk[(size_t)NMAX * 8];
__device__ float g_Sfv[GMAX * 8];
__device__ float g_Smin[GMAX * 8];
__device__ float g_Smax[GMAX * 8];
__device__ float g_h[GMAX * 64];
__device__ float g_bn[128];

__device__ __forceinline__ float sigmoidf_(float x) {
    return 1.0f / (1.0f + __expf(-x));
}

__device__ __forceinline__ unsigned long long pack2(float lo, float hi) {
    unsigned long long r;
    asm("mov.b64 %0, {%1, %2};" : "=l"(r) : "f"(lo), "f"(hi));
    return r;
}
__device__ __forceinline__ void unpack2(unsigned long long v, float& lo, float& hi) {
    asm("mov.b64 {%0, %1}, %2;" : "=f"(lo), "=f"(hi) : "l"(v));
}
__device__ __forceinline__ unsigned long long ffma2(unsigned long long a,
                                                    unsigned long long b,
                                                    unsigned long long c) {
    unsigned long long d;
    asm("fma.rn.f32x2 %0, %1, %2, %3;" : "=l"(d) : "l"(a), "l"(b), "l"(c));
    return d;
}

__device__ __forceinline__ void cp_async16(unsigned dst, const void* src, int nbytes) {
    asm volatile("cp.async.cg.shared.global [%0], [%1], 16, %2;"
                 :: "r"(dst), "l"(src), "r"(nbytes));
}
#define CP_COMMIT() asm volatile("cp.async.commit_group;" ::: "memory")
#define CP_WAIT0()  asm volatile("cp.async.wait_group 0;" ::: "memory")

// init sentinels + Sfv
__global__ void init_kernel(int n8, int g8) {
    int i = blockIdx.x * blockDim.x + threadIdx.x;
    if (i < n8) { g_mink[i] = 0x7f800000; g_maxk[i] = 0; }
    if (i < g8) g_Sfv[i] = 0.0f;
}

// no-op spacers so ncu's fixed capture slot (4th launch) lands on vertex_kernel
__global__ void spacer_kernel() {}
__global__ void spacer2_kernel() {}

// ---------------------------------------------------------------------------
// Persistent vertex kernel: FFMA2 GEMM, cp.async double-buffered tiles.
// NEW mapping (R9): tx = lane (32 distinct N-chunks of 4) so every lane's
// W LDS.128 is unique (no duplicated crossbar traffic); m0 = warp*8 so all
// x loads are full-warp broadcasts. Thread tile 8(M)x4(N).
// ---------------------------------------------------------------------------
#define XS_STRIDE 132
#define XS_FLOATS (128 * XS_STRIDE)      // 16896
#define W_OFF     (2 * XS_FLOATS)        // 33792
#define W2_OFF    (W_OFF + 16384)        // 50176
#define B1_OFF    (W2_OFF + 512)
#define B2_OFF    (B1_OFF + 64)
#define SMV_FLOATS (B2_OFF + 8)          // 50760 floats = 203040 B

__device__ __forceinline__ void prefetch_tile(const float* __restrict__ x,
                                              int v0, int N,
                                              unsigned xs_sm, int tid) {
#pragma unroll
    for (int i = 0; i < 8; ++i) {
        int c = tid + i * 512;           // 0..4095 chunk id
        int row = c >> 5, col4 = c & 31;
        unsigned dst = xs_sm + (unsigned)(row * XS_STRIDE + col4 * 4) * 4u;
        const float* src = x + (size_t)(v0 + row) * 128 + col4 * 4;
        int nb = (v0 + row < N) ? 16 : 0;   // zero-fill OOB rows
        cp_async16(dst, src, nb);
    }
}

__global__ __launch_bounds__(512) void vertex_kernel(
    const float* __restrict__ x, const int* __restrict__ batch,
    const float* __restrict__ W1, const float* __restrict__ b1,
    const float* __restrict__ W2, const float* __restrict__ b2,
    const float* __restrict__ We1, int N, int tiles)
{
    extern __shared__ float sm[];
    float* Wsm = sm + W_OFF;
    float* W2s = sm + W2_OFF;
    float* b1s = sm + B1_OFF;
    float* b2s = sm + B2_OFF;

    const int tid = threadIdx.x;
    const unsigned sm_base = (unsigned)__cvta_generic_to_shared(sm);

    // ---- stage weights once ----
    for (int i = tid; i < 16384; i += 512) {
        int k = i >> 7, n = i & 127;
        Wsm[i] = (n < 64) ? W1[k * 64 + n] : We1[k * 64 + (n - 64)];
    }
    if (tid < 512) W2s[tid] = W2[tid];
    if (tid < 64) b1s[tid] = b1[tid];
    if (tid < 8)  b2s[tid] = b2[tid];

    const int stride = gridDim.x;
    int pp = 0;
    if ((int)blockIdx.x < tiles)
        prefetch_tile(x, blockIdx.x * 128, N, sm_base, tid);
    CP_COMMIT();
    __syncthreads();   // weights + first-tile issue ordering

    const int tx = tid & 31;          // lane -> N chunk (32 x 4 cols)
    const int ty = tid >> 5;          // warp -> M chunk (16 x 8 rows)
    const int m0 = ty * 8, n0 = tx * 4;

    for (int t = blockIdx.x; t < tiles; t += stride) {
        CP_WAIT0();
        __syncthreads();   // xs[pp] ready for everyone; prior epilogue done

        int tn = t + stride;
        if (tn < tiles)
            prefetch_tile(x, tn * 128, N,
                          sm_base + (unsigned)((pp ^ 1) * XS_FLOATS) * 4u, tid);
        CP_COMMIT();

        float* xs   = sm + pp * XS_FLOATS;
        float* hbuf = xs;                   // reused after k-loop
        const int v0 = t * 128;

        unsigned long long acc[8][2];
#pragma unroll
        for (int mi = 0; mi < 8; ++mi) { acc[mi][0] = 0ULL; acc[mi][1] = 0ULL; }

#pragma unroll 2
        for (int k4 = 0; k4 < 128; k4 += 4) {
            float4 xr[8];
#pragma unroll
            for (int mi = 0; mi < 8; ++mi)
                xr[mi] = *reinterpret_cast<const float4*>(
                    xs + (m0 + mi) * XS_STRIDE + k4);   // warp-broadcast
#pragma unroll
            for (int kk = 0; kk < 4; ++kk) {
                float4 wa = *reinterpret_cast<const float4*>(
                    Wsm + ((k4 + kk) << 7) + n0);       // unique per lane
                unsigned long long w0 = pack2(wa.x, wa.y);
                unsigned long long w1p = pack2(wa.z, wa.w);
#pragma unroll
                for (int mi = 0; mi < 8; ++mi) {
                    float xv = (kk == 0) ? xr[mi].x
                             : (kk == 1) ? xr[mi].y
                             : (kk == 2) ? xr[mi].z : xr[mi].w;
                    unsigned long long xx = pack2(xv, xv);
                    acc[mi][0] = ffma2(xx, w0,  acc[mi][0]);
                    acc[mi][1] = ffma2(xx, w1p, acc[mi][1]);
                }
            }
        }
        __syncthreads();   // all reads of xs[pp] done before hbuf overwrite

        if (tx < 16) {
            // h1 cols 0..63 -> hbuf
#pragma unroll
            for (int mi = 0; mi < 8; ++mi) {
                float* dst = hbuf + (m0 + mi) * XS_STRIDE + n0;
                float l0, h0, l1, h1;
                unpack2(acc[mi][0], l0, h0);
                unpack2(acc[mi][1], l1, h1);
                dst[0] = l0; dst[1] = h0; dst[2] = l1; dst[3] = h1;
            }
        } else {
            // xW cols 64..127 -> global (coalesced 256B per row per warp-half)
#pragma unroll
            for (int mi = 0; mi < 8; ++mi) {
                int v = v0 + m0 + mi;
                if (v < N) {
                    float l0, h0, l1, h1;
                    unpack2(acc[mi][0], l0, h0);
                    unpack2(acc[mi][1], l1, h1);
                    *reinterpret_cast<float4*>(g_xW + (size_t)v * 64 + (n0 - 64)) =
                        make_float4(l0, h0, l1, h1);
                }
            }
        }
        __syncthreads();

        // fv epilogue: one vertex per thread (tid<128)
        if (tid < 128) {
            int v = v0 + tid;
            bool valid = (v < N);
            float a8[8];
#pragma unroll
            for (int f = 0; f < 8; ++f) a8[f] = b2s[f];
            const float* hr = hbuf + tid * XS_STRIDE;
#pragma unroll 4
            for (int k = 0; k < 64; ++k) {
                float hv = fmaxf(hr[k] + b1s[k], 0.0f);
#pragma unroll
                for (int f = 0; f < 8; ++f) a8[f] = fmaf(hv, W2s[k * 8 + f], a8[f]);
            }
#pragma unroll
            for (int f = 0; f < 8; ++f) a8[f] = valid ? sigmoidf_(a8[f]) : 0.0f;

            const unsigned m = 0xffffffffu;
            int lane = tid & 31;
            int gidx = batch[valid ? v : (N - 1)];
            int gl0  = __shfl_sync(m, gidx, 0);
            bool uni = __all_sync(m, gidx == gl0);
            if (uni) {
#pragma unroll
                for (int f = 0; f < 8; ++f) {
                    float s = a8[f];
                    s += __shfl_xor_sync(m, s, 16);
                    s += __shfl_xor_sync(m, s, 8);
                    s += __shfl_xor_sync(m, s, 4);
                    s += __shfl_xor_sync(m, s, 2);
                    s += __shfl_xor_sync(m, s, 1);
                    if (lane == 0) atomicAdd(&g_Sfv[gl0 * 8 + f], s);
                }
            } else if (valid) {
#pragma unroll
                for (int f = 0; f < 8; ++f) atomicAdd(&g_Sfv[gidx * 8 + f], a8[f]);
            }
        }
        pp ^= 1;
    }
}

// ---------------------------------------------------------------------------
// Edge kernel: 8 lanes cooperate per edge; h folded into fe (low live regs);
// natural register allocation (no min-blocks clamp — the R8 clamp spilled).
// ---------------------------------------------------------------------------
__global__ __launch_bounds__(256) void edge_kernel(
    const float* __restrict__ pos, const int* __restrict__ ei,
    const float* __restrict__ We1, const float* __restrict__ be1,
    const float* __restrict__ We2, const float* __restrict__ be2, int E)
{
    __shared__ __align__(16) float w1l[64];
    __shared__ __align__(16) float be1s[64];
    __shared__ float We2s[512];
    __shared__ float be2s[8];

    const int tid = threadIdx.x;
    for (int i = tid; i < 64; i += 256) { w1l[i] = We1[8192 + i]; be1s[i] = be1[i]; }
    for (int i = tid; i < 512; i += 256) We2s[i] = We2[i];
    if (tid < 8) be2s[tid] = be2[tid];
    __syncthreads();

    const int l = tid & 7;
    const int j0 = l * 8;
    const int egrp = (blockIdx.x * 256 + tid) >> 3;
    const int estride = (gridDim.x * 256) >> 3;
    const unsigned fullm = 0xffffffffu;

    for (int e = egrp; e < E; e += estride) {
        int s = ei[e], d = ei[E + e];
        float dx = pos[s * 3 + 0] - pos[d * 3 + 0];
        float dy = pos[s * 3 + 1] - pos[d * 3 + 1];
        float dz = pos[s * 3 + 2] - pos[d * 3 + 2];
        float dist = sqrtf(dx * dx + dy * dy + dz * dz);

        const float4* xs4 = reinterpret_cast<const float4*>(g_xW + (size_t)s * 64 + j0);
        const float4* xd4 = reinterpret_cast<const float4*>(g_xW + (size_t)d * 64 + j0);

        float fe[8];
#pragma unroll
        for (int f = 0; f < 8; ++f) fe[f] = 0.0f;

#pragma unroll
        for (int q = 0; q < 2; ++q) {
            float4 aa = xs4[q], bb = xd4[q];
            float4 wl = *reinterpret_cast<const float4*>(w1l + j0 + 4 * q);
            float4 bv = *reinterpret_cast<const float4*>(be1s + j0 + 4 * q);
            float h0 = fmaxf(fmaf(dist, wl.x, aa.x + bb.x) + bv.x, 0.0f);
            float h1 = fmaxf(fmaf(dist, wl.y, aa.y + bb.y) + bv.y, 0.0f);
            float h2 = fmaxf(fmaf(dist, wl.z, aa.z + bb.z) + bv.z, 0.0f);
            float h3 = fmaxf(fmaf(dist, wl.w, aa.w + bb.w) + bv.w, 0.0f);
            const float* w0r = We2s + (j0 + 4 * q) * 8;
#pragma unroll
            for (int f = 0; f < 8; ++f) {
                float acc = fmaf(h0, w0r[f], fe[f]);
                acc = fmaf(h1, w0r[8 + f], acc);
                acc = fmaf(h2, w0r[16 + f], acc);
                fe[f] = fmaf(h3, w0r[24 + f], acc);
            }
        }
#pragma unroll
        for (int f = 0; f < 8; ++f) {
            float v = fe[f];
            v += __shfl_xor_sync(fullm, v, 4);
            v += __shfl_xor_sync(fullm, v, 2);
            v += __shfl_xor_sync(fullm, v, 1);
            fe[f] = v;
        }
        int key = __float_as_int(sigmoidf_(fe[l] + be2s[l]));
        atomicMin(g_mink + (size_t)s * 8 + l, key);
        atomicMin(g_mink + (size_t)d * 8 + l, key);
        atomicMax(g_maxk + (size_t)s * 8 + l, key);
        atomicMax(g_maxk + (size_t)d * 8 + l, key);
    }
}

// ---------------------------------------------------------------------------
// Per-graph vertex reduce: fixup sentinels -> 1.0, sum dmin/dmax per graph
// ---------------------------------------------------------------------------
__global__ __launch_bounds__(256) void vreduce_kernel(const int* __restrict__ vs)
{
    __shared__ float rn[8], rx[8];
    const int tid = threadIdx.x, g = blockIdx.x;
    const int v0 = vs[g], v1 = vs[g + 1];
    if (tid < 8) { rn[tid] = 0.0f; rx[tid] = 0.0f; }
    __syncthreads();

    float ln[8], lx[8];
#pragma unroll
    for (int f = 0; f < 8; ++f) { ln[f] = 0.0f; lx[f] = 0.0f; }
    for (int v = v0 + tid; v < v1; v += 256) {
        const int4* mn = reinterpret_cast<const int4*>(g_mink + (size_t)v * 8);
        const int4* mx = reinterpret_cast<const int4*>(g_maxk + (size_t)v * 8);
        int4 a = mn[0], b = mn[1], c = mx[0], d = mx[1];
        ln[0] += (a.x == 0x7f800000) ? 1.0f : __int_as_float(a.x);
        ln[1] += (a.y == 0x7f800000) ? 1.0f : __int_as_float(a.y);
        ln[2] += (a.z == 0x7f800000) ? 1.0f : __int_as_float(a.z);
        ln[3] += (a.w == 0x7f800000) ? 1.0f : __int_as_float(a.w);
        ln[4] += (b.x == 0x7f800000) ? 1.0f : __int_as_float(b.x);
        ln[5] += (b.y == 0x7f800000) ? 1.0f : __int_as_float(b.y);
        ln[6] += (b.z == 0x7f800000) ? 1.0f : __int_as_float(b.z);
        ln[7] += (b.w == 0x7f800000) ? 1.0f : __int_as_float(b.w);
        lx[0] += (c.x == 0) ? 1.0f : __int_as_float(c.x);
        lx[1] += (c.y == 0) ? 1.0f : __int_as_float(c.y);
        lx[2] += (c.z == 0) ? 1.0f : __int_as_float(c.z);
        lx[3] += (c.w == 0) ? 1.0f : __int_as_float(c.w);
        lx[4] += (d.x == 0) ? 1.0f : __int_as_float(d.x);
        lx[5] += (d.y == 0) ? 1.0f : __int_as_float(d.y);
        lx[6] += (d.z == 0) ? 1.0f : __int_as_float(d.z);
        lx[7] += (d.w == 0) ? 1.0f : __int_as_float(d.w);
    }
    const unsigned m = 0xffffffffu;
    int lane = tid & 31;
#pragma unroll
    for (int f = 0; f < 8; ++f) {
        float s = ln[f];
        s += __shfl_xor_sync(m, s, 16); s += __shfl_xor_sync(m, s, 8);
        s += __shfl_xor_sync(m, s, 4);  s += __shfl_xor_sync(m, s, 2);
        s += __shfl_xor_sync(m, s, 1);
        if (lane == 0) atomicAdd(&rn[f], s);
        float t = lx[f];
        t += __shfl_xor_sync(m, t, 16); t += __shfl_xor_sync(m, t, 8);
        t += __shfl_xor_sync(m, t, 4);  t += __shfl_xor_sync(m, t, 2);
        t += __shfl_xor_sync(m, t, 1);
        if (lane == 0) atomicAdd(&rx[f], t);
    }
    __syncthreads();
    if (tid < 8) { g_Smin[g * 8 + tid] = rn[tid]; g_Smax[g * 8 + tid] = rx[tid]; }
}

// h = x0 + x1 (pre-BN)
__global__ void f1_kernel(const float* __restrict__ Wd0, const float* __restrict__ bd0,
                          const float* __restrict__ Wd1, const float* __restrict__ bd1,
                          const int* __restrict__ vs, const int* __restrict__ es)
{
    int g = blockIdx.x, o = threadIdx.x;
    float a = 0.0f;
#pragma unroll
    for (int f = 0; f < 8; ++f) {
        float sf = g_Sfv[g * 8 + f];
        float sx = g_Smax[g * 8 + f];
        float sn = g_Smin[g * 8 + f];
        a = fmaf(sf, Wd0[(4 * f + 1) * 64 + o], a);
        a = fmaf(sx, Wd0[(4 * f + 2) * 64 + o], a);
        a = fmaf(sn, Wd0[(4 * f + 3) * 64 + o], a);
    }
    int nv = vs[g + 1] - vs[g];
    int ne = es[g + 1] - es[g];
    float x0 = a / (float)nv + bd0[o];
    float x1 = (ne - (nv - 1) > 0)
                   ? (Wd1[64 + o] + Wd1[128 + o] + Wd1[192 + o] + bd1[o])
                   : 0.0f;
    g_h[g * 64 + o] = x0 + x1;
}

// BatchNorm stats (two-pass)
__global__ void bn_kernel(int G)
{
    __shared__ float ps[512];
    __shared__ float mu_s[64];
    int t = threadIdx.x, o = t & 63, grp = t >> 6;
    float s = 0.0f;
    for (int r = grp; r < G; r += 8) s += g_h[r * 64 + o];
    ps[t] = s;
    __syncthreads();
    if (t < 64) {
        float S = 0.0f;
        for (int k = 0; k < 8; ++k) S += ps[k * 64 + o];
        mu_s[o] = S / (float)G;
    }
    __syncthreads();
    float mu = mu_s[o];
    s = 0.0f;
    for (int r = grp; r < G; r += 8) { float d = g_h[r * 64 + o] - mu; s = fmaf(d, d, s); }
    ps[t] = s;
    __syncthreads();
    if (t < 64) {
        float S = 0.0f;
        for (int k = 0; k < 8; ++k) S += ps[k * 64 + o];
        g_bn[o] = mu_s[o];
        g_bn[64 + o] = rsqrtf(S / (float)G + 1e-5f);
    }
}

// normalize + out MLP
__global__ __launch_bounds__(1024) void out_kernel(
    const float* __restrict__ gamma, const float* __restrict__ beta,
    const float* __restrict__ Wo1, const float* __restrict__ bo1,
    const float* __restrict__ Wo2, const float* __restrict__ bo2,
    float* __restrict__ out, int G)
{
    __shared__ float hn[16][64];
    __shared__ float t1[16][64];
    int t = threadIdx.x, gl = t >> 6, o = t & 63;
    int g = blockIdx.x * 16 + gl;
    float v = 0.0f;
    if (g < G) v = (g_h[g * 64 + o] - g_bn[o]) * g_bn[64 + o] * gamma[o] + beta[o];
    hn[gl][o] = v;
    __syncthreads();
    float a = bo1[o];
#pragma unroll 8
    for (int k = 0; k < 64; ++k) a = fmaf(hn[gl][k], Wo1[k * 64 + o], a);
    t1[gl][o] = fmaxf(a, 0.0f);
    __syncthreads();
    float b = bo2[o];
#pragma unroll 8
    for (int k = 0; k < 64; ++k) b = fmaf(t1[gl][k], Wo2[k * 64 + o], b);
    if (g < G) out[g * 64 + o] = b;
}

extern "C" void kernel_launch(void* const* d_in, const int* in_sizes, int n_in,
                              void* d_out, int out_size)
{
    const float* x     = (const float*)d_in[0];
    const float* pos   = (const float*)d_in[1];
    const int*   ei    = (const int*)d_in[2];
    const int*   vs    = (const int*)d_in[3];
    const int*   es    = (const int*)d_in[4];
    const int*   batch = (const int*)d_in[5];
    const float* W1  = (const float*)d_in[6];
    const float* b1  = (const float*)d_in[7];
    const float* W2  = (const float*)d_in[8];
    const float* b2  = (const float*)d_in[9];
    const float* We1 = (const float*)d_in[10];
    const float* be1 = (const float*)d_in[11];
    const float* We2 = (const float*)d_in[12];
    const float* be2 = (const float*)d_in[13];
    const float* Wd0 = (const float*)d_in[14];
    const float* bd0 = (const float*)d_in[15];
    const float* Wd1 = (const float*)d_in[16];
    const float* bd1 = (const float*)d_in[17];
    const float* gm  = (const float*)d_in[18];
    const float* bt  = (const float*)d_in[19];
    const float* Wo1 = (const float*)d_in[20];
    const float* bo1 = (const float*)d_in[21];
    const float* Wo2 = (const float*)d_in[22];
    const float* bo2 = (const float*)d_in[23];

    int N = in_sizes[0] / 128;
    int E = in_sizes[2] / 2;
    int G = out_size / 64;
    int tiles = (N + 127) / 128;

    init_kernel<<<(N * 8 + 255) / 256, 256>>>(N * 8, G * 8);   // launch 1
    spacer_kernel<<<1, 32>>>();                                 // launch 2
    spacer2_kernel<<<1, 32>>>();                                // launch 3

    size_t smv = (size_t)SMV_FLOATS * sizeof(float);
    cudaFuncSetAttribute(vertex_kernel, cudaFuncAttributeMaxDynamicSharedMemorySize, (int)smv);
    vertex_kernel<<<148, 512, smv>>>(x, batch, W1, b1, W2, b2, We1, N, tiles); // launch 4 (ncu slot)

    edge_kernel<<<1024, 256>>>(pos, ei, We1, be1, We2, be2, E); // launch 5
    vreduce_kernel<<<G, 256>>>(vs);
    f1_kernel<<<G, 64>>>(Wd0, bd0, Wd1, bd1, vs, es);
    bn_kernel<<<1, 512>>>(G);
    out_kernel<<<(G + 15) / 16, 1024>>>(gm, bt, Wo1, bo1, Wo2, bo2, (float*)d_out, G);
}